// round 1
// baseline (speedup 1.0000x reference)
#include <cuda_runtime.h>

// HawkesKT fused kernel: gathered dual-GEMM (alpha & beta packed in f32x2)
// + exponential-decay elementwise + masked (i<j) column reduction + sigmoid.
//
// Shapes: B=64, L=1024, E=128, N_SKILLS=1000.
// input int32 [B,4,L] = {skills, problems, labels, times}.

#define NB   64
#define SEQL 1024
#define EMB  128
#define NSK  1000

typedef unsigned long long ull;

// Packed fp32x2 FMA (Blackwell sm_100+): c.lo += a.lo*b.lo ; c.hi += a.hi*b.hi
__device__ __forceinline__ void fma2(ull &c, ull a, ull b) {
    asm("fma.rn.f32x2 %0, %1, %2, %0;" : "+l"(c) : "l"(a), "l"(b));
}
__device__ __forceinline__ ull pack2(float lo, float hi) {
    ull r; asm("mov.b64 %0, {%1, %2};" : "=l"(r) : "f"(lo), "f"(hi)); return r;
}
__device__ __forceinline__ float2 unpack2(ull v) {
    float lo, hi; asm("mov.b64 {%0, %1}, %2;" : "=f"(lo), "=f"(hi) : "l"(v));
    return make_float2(lo, hi);
}

// Shared memory layout (bytes):
//   sJ : 128 k-rows x 128 ull  (j-side, full K, (alpha,beta) interleaved) = 131072
//   sI : 64  k-rows x 128 ull  (i-side, one K-chunk)                      = 65536
//   ts : 1024 int                                                          = 4096
//   red: 16 x 128 float                                                    = 8192
#define SJ_OFF  0
#define SI_OFF  131072
#define TS_OFF  (131072 + 65536)
#define RED_OFF (131072 + 65536 + 4096)
#define SMEM_BYTES (131072 + 65536 + 4096 + 8192)

__global__ void __launch_bounds__(256, 1)
hawkes_fused(const int*   __restrict__ input,
             const float* __restrict__ problem_base,
             const float* __restrict__ skill_base,
             const float* __restrict__ alpha_inter,
             const float* __restrict__ alpha_skill,
             const float* __restrict__ beta_inter,
             const float* __restrict__ beta_skill,
             float*       __restrict__ out)
{
    extern __shared__ char smem[];
    ull*   sJ  = (ull*)(smem + SJ_OFF);
    ull*   sI  = (ull*)(smem + SI_OFF);
    int*   ts  = (int*)(smem + TS_OFF);
    float* red = (float*)(smem + RED_OFF);

    const int tid = threadIdx.x;
    const int tx  = tid & 15;     // j micro-tile selector (8 j's)
    const int ty  = tid >> 4;     // i micro-tile selector (8 i's)
    const int jt  = blockIdx.x;   // j tile 0..7
    const int b   = blockIdx.y;   // batch
    const int* __restrict__ inp = input + b * 4 * SEQL;

    // ---- load times for this batch ----
    for (int i = tid; i < SEQL; i += 256) ts[i] = inp[3 * SEQL + i];

    // ---- gather j-side tiles (alpha_skill/beta_skill rows), full K, once ----
    {
        const int jl = tid & 127;
        const int kh = tid >> 7;                 // which K half this thread fills
        const int jg = jt * 128 + jl;
        const int sk = inp[jg];
        const float4* As = (const float4*)(alpha_skill + sk * EMB) + kh * 16;
        const float4* Bs = (const float4*)(beta_skill  + sk * EMB) + kh * 16;
        // permuted float2-index so that warp frag loads are conflict-free:
        const int s = ((jl & 7) << 4) + (jl >> 3);
#pragma unroll
        for (int q = 0; q < 16; ++q) {
            float4 a = As[q];
            float4 c = Bs[q];
            int k0 = kh * 64 + q * 4;
            sJ[(k0 + 0) * 128 + s] = pack2(a.x, c.x);
            sJ[(k0 + 1) * 128 + s] = pack2(a.y, c.y);
            sJ[(k0 + 2) * 128 + s] = pack2(a.z, c.z);
            sJ[(k0 + 3) * 128 + s] = pack2(a.w, c.w);
        }
    }

    float csum[8];
#pragma unroll
    for (int jj = 0; jj < 8; ++jj) csum[jj] = 0.0f;

    __syncthreads();   // ts + sJ visible

    int tj[8];
#pragma unroll
    for (int jj = 0; jj < 8; ++jj) tj[jj] = ts[jt * 128 + tx * 8 + jj];

    // ---- triangular loop over i tiles ----
    for (int it = 0; it <= jt; ++it) {
        ull acc[8][8];
#pragma unroll
        for (int ii = 0; ii < 8; ++ii)
#pragma unroll
            for (int jj = 0; jj < 8; ++jj) acc[ii][jj] = 0ULL;

#pragma unroll 1
        for (int kc = 0; kc < 2; ++kc) {
            __syncthreads();   // protect sI from previous k-loop readers
            {
                const int il = tid & 127;
                const int kh = tid >> 7;
                const int ig = it * 128 + il;
                const int sk  = inp[ig];
                const int lab = inp[2 * SEQL + ig];
                const int inter = sk + ((lab < 2) ? lab : 0) * NSK;
                const float4* Ai = (const float4*)(alpha_inter + inter * EMB) + kc * 16 + kh * 8;
                const float4* Bi = (const float4*)(beta_inter  + inter * EMB) + kc * 16 + kh * 8;
#pragma unroll
                for (int q = 0; q < 8; ++q) {
                    float4 a = Ai[q];
                    float4 c = Bi[q];
                    int k0 = kh * 32 + q * 4;
                    sI[(k0 + 0) * 128 + il] = pack2(a.x, c.x);
                    sI[(k0 + 1) * 128 + il] = pack2(a.y, c.y);
                    sI[(k0 + 2) * 128 + il] = pack2(a.z, c.z);
                    sI[(k0 + 3) * 128 + il] = pack2(a.w, c.w);
                }
            }
            __syncthreads();

            const ull* __restrict__ Jrow = sJ + (kc * 64) * 128;
#pragma unroll 4
            for (int k = 0; k < 64; ++k) {
                ull bfr[8], afr[8];
#pragma unroll
                for (int jj = 0; jj < 8; ++jj) bfr[jj] = Jrow[k * 128 + jj * 16 + tx];
#pragma unroll
                for (int ii = 0; ii < 8; ++ii) afr[ii] = sI[k * 128 + ty * 8 + ii];
#pragma unroll
                for (int ii = 0; ii < 8; ++ii)
#pragma unroll
                    for (int jj = 0; jj < 8; ++jj)
                        fma2(acc[ii][jj], afr[ii], bfr[jj]);
            }
        }

        // ---- epilogue for this i-tile: decay + masked column accumulation ----
        const int ibase = it * 128 + ty * 8;
        const int jbase = jt * 128 + tx * 8;
#pragma unroll
        for (int ii = 0; ii < 8; ++ii) {
            const int ig  = ibase + ii;
            const int ti_ = ts[ig];
#pragma unroll
            for (int jj = 0; jj < 8; ++jj) {
                const int jg = jbase + jj;
                if (ig < jg) {
                    float2 ab  = unpack2(acc[ii][jj]);   // x = alpha dot, y = beta dot
                    float dtf  = fabsf((float)(ti_ - tj[jj]));
                    float ldt  = __logf(dtf + 1e-10f) * 0.6213349345596119f; // 1/ln(5)
                    float beta = fminf(fmaxf(ab.y + 1.0f, 0.0f), 10.0f);
                    csum[jj] += ab.x * __expf(-beta * ldt);
                }
            }
        }
    }

    // ---- cross-thread column reduction + bias + sigmoid ----
    __syncthreads();
#pragma unroll
    for (int jj = 0; jj < 8; ++jj) red[ty * 128 + tx * 8 + jj] = csum[jj];
    __syncthreads();

    if (tid < 128) {
        const int jg = jt * 128 + tid;
        float s = 0.0f;
#pragma unroll
        for (int r = 0; r < 16; ++r) s += red[r * 128 + tid];
        const int sk = inp[jg];
        const int pr = inp[SEQL + jg];
        float x = problem_base[pr] + skill_base[sk] + s;
        out[b * SEQL + jg] = 1.0f / (1.0f + __expf(-x));
    }
}

extern "C" void kernel_launch(void* const* d_in, const int* in_sizes, int n_in,
                              void* d_out, int out_size) {
    const int*   input        = (const int*)  d_in[0];
    const float* problem_base = (const float*)d_in[1];
    const float* skill_base   = (const float*)d_in[2];
    const float* alpha_inter  = (const float*)d_in[3];
    const float* alpha_skill  = (const float*)d_in[4];
    const float* beta_inter   = (const float*)d_in[5];
    const float* beta_skill   = (const float*)d_in[6];
    float* outp = (float*)d_out;

    cudaFuncSetAttribute(hawkes_fused,
                         cudaFuncAttributeMaxDynamicSharedMemorySize, SMEM_BYTES);

    dim3 grid(SEQL / 128, NB);
    hawkes_fused<<<grid, 256, SMEM_BYTES>>>(input, problem_base, skill_base,
                                            alpha_inter, alpha_skill,
                                            beta_inter, beta_skill, outp);
}

// round 6
// speedup vs baseline: 3.7371x; 3.7371x over previous
#include <cuda_runtime.h>
#include <cuda_fp16.h>
#include <cstdint>

// HawkesKT via warp-level HMMA (mma.sync m16n8k16 f16): per CTA = (j-tile 128, batch).
// Dual GEMM D[j,i] = dot(skill_tab[j], inter_tab[i]) for alpha & beta, accumulated in
// registers; fused decay epilogue + masked (i<j) reduction over i.
// B=64, L=1024, E=128.

#define NB   64
#define SEQL 1024
#define EMB  128
#define NSK  1000

#define PITCH 272   // bytes per tile row (136 f16) -> conflict-free ldmatrix

// smem offsets (bytes)
#define SJA 0
#define SJB 34816
#define SIA 69632
#define SIB 104448
#define TSF 139264          // 1024 float times
#define RED 143360          // 2 x 128 float
#define SMEM_BYTES 144384

__device__ __forceinline__ uint32_t smem_u32(const void* p) {
    uint32_t a;
    asm("{ .reg .u64 t; cvta.to.shared.u64 t, %1; cvt.u32.u64 %0, t; }" : "=r"(a) : "l"(p));
    return a;
}
__device__ __forceinline__ uint32_t pkh(float lo, float hi) {
    uint32_t r;
    asm("cvt.rn.f16x2.f32 %0, %1, %2;" : "=r"(r) : "f"(hi), "f"(lo)); // first src -> upper
    return r;
}
__device__ __forceinline__ void ldm_x4(uint32_t* r, uint32_t a) {
    asm volatile("ldmatrix.sync.aligned.m8n8.x4.shared.b16 {%0,%1,%2,%3}, [%4];"
                 : "=r"(r[0]), "=r"(r[1]), "=r"(r[2]), "=r"(r[3]) : "r"(a));
}
__device__ __forceinline__ void mma16816(float* c, const uint32_t* a, const uint32_t* b) {
    asm volatile(
        "mma.sync.aligned.m16n8k16.row.col.f32.f16.f16.f32 "
        "{%0,%1,%2,%3}, {%4,%5,%6,%7}, {%8,%9}, {%0,%1,%2,%3};"
        : "+f"(c[0]), "+f"(c[1]), "+f"(c[2]), "+f"(c[3])
        : "r"(a[0]), "r"(a[1]), "r"(a[2]), "r"(a[3]), "r"(b[0]), "r"(b[1]));
}
__device__ __forceinline__ float lg2f(float x) {
    float r; asm("lg2.approx.f32 %0, %1;" : "=f"(r) : "f"(x)); return r;
}
__device__ __forceinline__ float ex2f(float x) {
    float r; asm("ex2.approx.f32 %0, %1;" : "=f"(r) : "f"(x)); return r;
}

// Gather one table row (128 fp32) -> f16 row-major tile (PITCH-byte rows).
// r = row 0..127, h = k-half 0/1.
__device__ __forceinline__ void gather_half(const float* __restrict__ src,
                                            char* __restrict__ dstTile, int r, int h) {
    const float4* s4 = (const float4*)src + h * 16;
    char* dst = dstTile + r * PITCH + h * 128;
#pragma unroll
    for (int q = 0; q < 8; ++q) {
        float4 v0 = s4[q * 2];
        float4 v1 = s4[q * 2 + 1];
        uint4 w;
        w.x = pkh(v0.x, v0.y);
        w.y = pkh(v0.z, v0.w);
        w.z = pkh(v1.x, v1.y);
        w.w = pkh(v1.z, v1.w);
        *(uint4*)(dst + q * 16) = w;
    }
}

__global__ void __launch_bounds__(256, 1)
hawkes_hmma(const int*   __restrict__ input,
            const float* __restrict__ problem_base,
            const float* __restrict__ skill_base,
            const float* __restrict__ alpha_inter,
            const float* __restrict__ alpha_skill,
            const float* __restrict__ beta_inter,
            const float* __restrict__ beta_skill,
            float*       __restrict__ out)
{
    extern __shared__ char smem[];
    float* tsf = (float*)(smem + TSF);
    float* red = (float*)(smem + RED);
    const uint32_t sbase = smem_u32(smem);

    const int tid  = threadIdx.x;
    const int wid  = tid >> 5;
    const int lane = tid & 31;
    const int jt   = (int)gridDim.x - 1 - (int)blockIdx.x;   // heavy tiles first
    const int b    = blockIdx.y;
    const int* __restrict__ inp = input + b * 4 * SEQL;

    const int Mw = (wid & 3) * 32;    // warp j-base within tile
    const int Nw = (wid >> 2) * 64;   // warp i-base within tile
    const int g  = lane >> 2;
    const int t  = lane & 3;

    // ---- times (as float) ----
    for (int i = tid; i < SEQL; i += 256) tsf[i] = (float)inp[3 * SEQL + i];

    // ---- j-side gather (alpha_skill / beta_skill) once ----
    {
        const int r = tid >> 1, h = tid & 1;
        const int sk = inp[jt * 128 + r];
        gather_half(alpha_skill + (size_t)sk * EMB, smem + SJA, r, h);
        gather_half(beta_skill  + (size_t)sk * EMB, smem + SJB, r, h);
    }
    __syncthreads();

    // ldmatrix per-thread base addresses
    // A (j-side): lanes 0-15 -> rows (m), lanes 16-31 -> k-half 1
    const uint32_t aRow = sbase + ((uint32_t)(Mw + (lane & 15)) * PITCH) + ((lane >> 4) & 1) * 16;
    // B (i-side, [n][k] row-major, NON-trans ldmatrix):
    //   lanes 0-7:  n 0-7,  k 0-7    lanes 8-15:  n 0-7,  k 8-15
    //   lanes 16-23:n 8-15, k 0-7    lanes 24-31: n 8-15, k 8-15
    const uint32_t bRow = sbase + ((uint32_t)(Nw + (lane & 7) + ((lane >> 4) & 1) * 8) * PITCH)
                                + ((lane >> 3) & 1) * 16;

    // accumulators: ca/cb[mt][nt][4]
    float ca[2][8][4], cb[2][8][4];
    float csum[4] = {0.f, 0.f, 0.f, 0.f};

    // j-row times for this lane (4 rows: mt*16 + rp*8 + g)
    const int jtb = jt * 128;
    float tjf[4];
#pragma unroll
    for (int q = 0; q < 4; ++q) tjf[q] = tsf[jtb + Mw + (q >> 1) * 16 + (q & 1) * 8 + g];
    // global j indices for mask (diag tiles)
    int jr[4];
#pragma unroll
    for (int q = 0; q < 4; ++q) jr[q] = Mw + (q >> 1) * 16 + (q & 1) * 8 + g;

    const float C1 = 0.6213349345596119f;  // 1/ln(5)

    for (int it = 0; it <= jt; ++it) {
        // ---- i-side gather ----
        {
            const int r = tid >> 1, h = tid & 1;
            const int ig = it * 128 + r;
            const int sk  = inp[ig];
            const int lab = inp[2 * SEQL + ig];
            const int inter = sk + ((lab < 2) ? lab : 0) * NSK;
            gather_half(alpha_inter + (size_t)inter * EMB, smem + SIA, r, h);
            gather_half(beta_inter  + (size_t)inter * EMB, smem + SIB, r, h);
        }
        __syncthreads();

        // ---- zero accum + mainloop ----
#pragma unroll
        for (int mt = 0; mt < 2; ++mt)
#pragma unroll
            for (int nt = 0; nt < 8; ++nt)
#pragma unroll
                for (int e = 0; e < 4; ++e) { ca[mt][nt][e] = 0.f; cb[mt][nt][e] = 0.f; }

#pragma unroll
        for (int ks = 0; ks < 8; ++ks) {
            uint32_t Aa[2][4], Ab[2][4];
#pragma unroll
            for (int mt = 0; mt < 2; ++mt) {
                uint32_t ao = aRow + (uint32_t)mt * 16 * PITCH + (uint32_t)ks * 32;
                ldm_x4(Aa[mt], SJA + ao);
                ldm_x4(Ab[mt], SJB + ao);
            }
#pragma unroll
            for (int np = 0; np < 4; ++np) {
                uint32_t Ba[4], Bb[4];
                uint32_t bo = bRow + (uint32_t)np * 16 * PITCH + (uint32_t)ks * 32;
                ldm_x4(Ba, SIA + bo);     // NON-trans: [n][k] row-major is already B col-major
                ldm_x4(Bb, SIB + bo);
#pragma unroll
                for (int mt = 0; mt < 2; ++mt) {
                    mma16816(ca[mt][np * 2 + 0], Aa[mt], Ba + 0);
                    mma16816(ca[mt][np * 2 + 1], Aa[mt], Ba + 2);
                    mma16816(cb[mt][np * 2 + 0], Ab[mt], Bb + 0);
                    mma16816(cb[mt][np * 2 + 1], Ab[mt], Bb + 2);
                }
            }
        }

        // ---- epilogue: decay + masked reduce over i ----
        const int itb = it * 128;
        float tif[16];
#pragma unroll
        for (int nt = 0; nt < 8; ++nt) {
            tif[nt * 2 + 0] = tsf[itb + Nw + nt * 8 + 2 * t + 0];
            tif[nt * 2 + 1] = tsf[itb + Nw + nt * 8 + 2 * t + 1];
        }
        const bool diag = (it == jt);
#pragma unroll
        for (int mt = 0; mt < 2; ++mt)
#pragma unroll
            for (int nt = 0; nt < 8; ++nt)
#pragma unroll
                for (int e = 0; e < 4; ++e) {
                    const int q  = mt * 2 + (e >> 1);
                    const int ic = nt * 2 + (e & 1);
                    float d   = tif[ic] - tjf[q];
                    float l2  = lg2f(fabsf(d) + 1e-10f);
                    float bcs = fminf(fmaxf(cb[mt][nt][e] * C1 + C1, 0.0f), 10.0f * C1);
                    float dec = ex2f(-bcs * l2);
                    float contrib = ca[mt][nt][e] * dec;
                    if (diag) {
                        // need i < j within the tile
                        if ((Nw + nt * 8 + 2 * t + (e & 1)) < jr[q]) csum[q] += contrib;
                    } else {
                        csum[q] += contrib;
                    }
                }
        __syncthreads();   // all warps done with sI before next gather overwrites
    }

    // ---- reduce csum across quad lanes (same row g, cols t=0..3) ----
#pragma unroll
    for (int q = 0; q < 4; ++q) {
        csum[q] += __shfl_xor_sync(0xFFFFFFFFu, csum[q], 1);
        csum[q] += __shfl_xor_sync(0xFFFFFFFFu, csum[q], 2);
    }
    const int wn = wid >> 2;
    if (t == 0) {
#pragma unroll
        for (int q = 0; q < 4; ++q)
            red[wn * 128 + Mw + (q >> 1) * 16 + (q & 1) * 8 + g] = csum[q];
    }
    __syncthreads();

    if (tid < 128) {
        const int j = jtb + tid;
        float s = red[tid] + red[128 + tid];
        const int sk = inp[j];
        const int pr = inp[SEQL + j];
        float x = problem_base[pr] + skill_base[sk] + s;
        out[b * SEQL + j] = 1.0f / (1.0f + ex2f(-1.4426950408889634f * x));
    }
}

extern "C" void kernel_launch(void* const* d_in, const int* in_sizes, int n_in,
                              void* d_out, int out_size) {
    const int*   input        = (const int*)  d_in[0];
    const float* problem_base = (const float*)d_in[1];
    const float* skill_base   = (const float*)d_in[2];
    const float* alpha_inter  = (const float*)d_in[3];
    const float* alpha_skill  = (const float*)d_in[4];
    const float* beta_inter   = (const float*)d_in[5];
    const float* beta_skill   = (const float*)d_in[6];
    float* outp = (float*)d_out;

    cudaFuncSetAttribute(hawkes_hmma,
                         cudaFuncAttributeMaxDynamicSharedMemorySize, SMEM_BYTES);

    dim3 grid(SEQL / 128, NB);
    hawkes_hmma<<<grid, 256, SMEM_BYTES>>>(input, problem_base, skill_base,
                                           alpha_inter, alpha_skill,
                                           beta_inter, beta_skill, outp);
}